// round 17
// baseline (speedup 1.0000x reference)
#include <cuda_runtime.h>
#include <cstddef>
#include <cstring>

#define Bv 32
#define Tv 512
#define Cv 8
#define Hv 256
#define Gv 1024

// ---------------- scratch (device globals: allocation-free) ----------------
__device__ float g_h1[(size_t)Tv * Cv * Hv * Bv];    // layer1 hidden, [T][C][H][B]
__device__ float g_hbuf[2 * Cv * Hv * Bv];           // h exchange, [2][C][H][B]
__device__ float g_opart[(size_t)Tv * Cv * 16 * Bv]; // head partials [T][C][rank][B]
__device__ unsigned g_cnt[Cv];                       // barrier counters (zero-init)
__device__ unsigned g_sense[Cv];                     // barrier sense (zero-init)

// ---------------- math helpers ----------------
__device__ __forceinline__ float sig_(float x) {
    return __fdividef(1.0f, 1.0f + __expf(-x));
}
__device__ __forceinline__ float tanh_(float x) {
    float ax = fabsf(x);
    float e  = __expf(-2.0f * ax);
    float t  = __fdividef(1.0f - e, 1.0f + e);
    return copysignf(t, x);
}
__device__ __forceinline__ float2 u2f(unsigned long long u) {
    float2 f; memcpy(&f, &u, 8); return f;
}

// packed fp32x2 FMA (FFMA2) and operand duplication
#define FMA2(acc, h, w) asm("fma.rn.f32x2 %0, %1, %2, %0;" : "+l"(acc) : "l"(h), "l"(w))
#define PACK2(d, s)     asm("mov.b64 %0, {%1, %1};" : "=l"(d) : "f"(s))

// cp.async helpers
__device__ __forceinline__ unsigned smem_u32(const void* p) {
    unsigned r;
    asm("{ .reg .u64 t; cvta.to.shared.u64 t, %1; cvt.u32.u64 %0, t; }" : "=r"(r) : "l"(p));
    return r;
}
__device__ __forceinline__ void cp16(unsigned s, const void* g) {
    asm volatile("cp.async.cg.shared.global [%0], [%1], 16;" :: "r"(s), "l"(g));
}
#define CP_COMMIT() asm volatile("cp.async.commit_group;" ::: "memory")
#define CP_WAIT0()  asm volatile("cp.async.wait_group 0;" ::: "memory")

// per-channel sense-reversing barrier (R7/R16-proven, BYTE-IDENTICAL) — used by L1
__device__ __forceinline__ void chan_barrier(int c, unsigned &lsense) {
    __syncthreads();
    if (threadIdx.x == 0) {
        __threadfence();
        unsigned a = atomicAdd(&g_cnt[c], 1u);
        if (a == 15u) {
            *(volatile unsigned*)&g_cnt[c] = 0u;
            __threadfence();
            *(volatile unsigned*)&g_sense[c] = lsense ^ 1u;
        } else {
            while (*(volatile unsigned*)&g_sense[c] == lsense) { __nanosleep(20); }
            __threadfence();
        }
    }
    lsense ^= 1u;
    __syncthreads();
}

// row permutation for W smem / gate buffers: lo-quads then hi-quads per row-oct
__host__ __device__ __forceinline__ int permr(int r) {
    return ((r >> 3) << 2) + (r & 3) + (((r >> 2) & 1) << 5);
}

// ---------------- smem layout (floats) ----------------
#define GSTR 68
#define SM_FLOATS (16384 + 16384 + 8192 + 8192 + 3 * (Bv * GSTR) + 512 + 64 + 64 + 32 + 16)
#define SM_BYTES  (SM_FLOATS * 4)   // 225,472 B

// matvec: 8 rows (8rg..8rg+7, perm-stored) x 2 batches (b2, b2+1) over one k-quarter.
// acc[q]   (q=0..3): f32x2 rows (8rg+2q, 8rg+2q+1), batch b2
// acc[4+q]          : same rows, batch b2+1
__device__ __forceinline__ void matvec8x2(unsigned long long* acc,
                                          const float* __restrict__ Wq,
                                          const float* __restrict__ Hq,
                                          int rg4, int b2)
{
    const float* wh = Wq + rg4;
    const float* hp = Hq + b2;
    #pragma unroll 4
    for (int kk = 0; kk < 64; ++kk) {
        ulonglong2 wlo = *(const ulonglong2*)wh;          // rows 8rg+0..3
        ulonglong2 whi = *(const ulonglong2*)(wh + 32);   // rows 8rg+4..7
        wh += 64;
        float2 hv = *(const float2*)hp;  hp += 32;
        unsigned long long hd0, hd1;
        PACK2(hd0, hv.x); PACK2(hd1, hv.y);
        FMA2(acc[0], hd0, wlo.x); FMA2(acc[1], hd0, wlo.y);
        FMA2(acc[2], hd0, whi.x); FMA2(acc[3], hd0, whi.y);
        FMA2(acc[4], hd1, wlo.x); FMA2(acc[5], hd1, wlo.y);
        FMA2(acc[6], hd1, whi.x); FMA2(acc[7], hd1, whi.y);
    }
}

template <int LAYER>
__global__ __launch_bounds__(512, 1)
void lstm_kernel(const float* __restrict__ x,
                 const float* __restrict__ Wih,   // L1: [C][G][1]; L2: [C][G][H]
                 const float* __restrict__ Whh,   // [C][G][H]
                 const float* __restrict__ bih,   // [C][G]
                 const float* __restrict__ bhh,   // [C][G]
                 const float* __restrict__ Wlin)  // [C][H]  (L2)
{
    extern __shared__ float sm[];
    float* Whh_s  = sm;
    float* Wih_s  = Whh_s + 16384;
    float* h_s    = Wih_s + 16384;
    float* h1_s   = h_s   + 8192;
    float* gsm    = h1_s  + 8192;
    float* part0  = gsm   + Bv * GSTR;
    float* part1  = part0 + Bv * GSTR;
    float* c_s    = part1 + Bv * GSTR;
    float* bsum   = c_s   + 512;
    float* wih1s  = bsum  + 64;
    float* xs     = wih1s + 64;
    float* wlin16 = xs    + 32;

    const int tid   = threadIdx.x;
    const int c     = blockIdx.x >> 4;
    const int rank  = blockIdx.x & 15;
    const int jbase = rank << 4;

    // NEW decomposition: lane = (rg, bp); warp = (bo, kq)
    const int lane = tid & 31;
    const int warp = tid >> 5;
    const int rg   = lane >> 2;          // row-oct: rows 8rg..8rg+7
    const int bp   = lane & 3;           // batch pair within octet
    const int kq   = warp & 3;           // k-quarter
    const int bo   = warp >> 2;          // batch octet
    const int rg4  = rg << 2;            // perm lo-block offset
    const int b2   = (bo << 3) + (bp << 1);   // first batch

    // activation decomposition (coalesced global stores)
    const int ab = tid & 31;
    const int aj = tid >> 5;

    // ---- init: weights k-major row-permuted, biases, zero state ----
    for (int idx = tid; idx < 64 * Hv; idx += 512) {
        int k  = idx >> 6;
        int r  = idx & 63;
        int g  = r >> 4;
        int jl = r & 15;
        size_t grow = (size_t)c * Gv + g * Hv + (jbase + jl);
        int pos = k * 64 + permr(r);
        Whh_s[pos] = Whh[grow * Hv + k];
        if (LAYER == 2)
            Wih_s[pos] = Wih[grow * Hv + k];
    }
    if (tid < 64) {
        int g = tid >> 4, jl = tid & 15;
        size_t gi = (size_t)c * Gv + g * Hv + (jbase + jl);
        bsum[tid] = bih[gi] + bhh[gi];
        if (LAYER == 1) wih1s[tid] = Wih[gi];
    }
    if (LAYER == 2 && tid < 16) wlin16[tid] = Wlin[c * Hv + jbase + tid];
    for (int i = tid; i < Hv * Bv; i += 512) h_s[i] = 0.0f;
    c_s[tid] = 0.0f;
    __syncthreads();

    const unsigned h1s_addr = smem_u32(h1_s) + (unsigned)tid * 16u;
    const int pbase = permr(aj);         // act read base; rows 16g+aj at pbase+8g

    unsigned long long Bk[8];
    #pragma unroll
    for (int i = 0; i < 8; ++i) Bk[i] = 0ull;

    // ---- pre-loop: stage inputs for step 0; L2 precomputes ih(h1[0]) ----
    float xr = 0.0f;
    if (LAYER == 2) {
        const float* src = g_h1 + ((size_t)0 * Cv + c) * (Hv * Bv) + tid * 4;
        #pragma unroll
        for (int i = 0; i < 4; ++i) cp16(h1s_addr + i * 512u * 16u, src + i * 512 * 4);
        CP_COMMIT(); CP_WAIT0();
        __syncthreads();
        matvec8x2(Bk, Wih_s + kq * 4096, h1_s + kq * 2048, rg4, b2);
        __syncthreads();   // ih(0) reads done before h1_s is overwritten
    } else {
        if (tid < Bv) xr = __ldg(&x[(size_t)tid * Tv * Cv + c]);
    }

    unsigned lsense = 0;

    for (int t = 0; t < Tv; ++t) {
        // ---- L2: issue prefetch of h1[t+1] (h1_s free: ih(t) consumed) ----
        if (LAYER == 2 && t + 1 < Tv) {
            const float* src = g_h1 + ((size_t)(t + 1) * Cv + c) * (Hv * Bv) + tid * 4;
            #pragma unroll
            for (int i = 0; i < 4; ++i) cp16(h1s_addr + i * 512u * 16u, src + i * 512 * 4);
            CP_COMMIT();
        }
        if (LAYER == 1) { if (tid < Bv) xs[tid] = xr; }
        __syncthreads();   // h_s reload (prev step) + staged inputs visible

        // ---- hh mat-vec ----
        unsigned long long A[8];
        #pragma unroll
        for (int i = 0; i < 8; ++i) A[i] = 0ull;
        matvec8x2(A, Whh_s + kq * 4096, h_s + kq * 2048, rg4, b2);

        // merge hh + carried ih accumulators
        float2 R[8];
        #pragma unroll
        for (int i = 0; i < 8; ++i) {
            float2 fa = u2f(A[i]);
            if (LAYER == 2) { float2 fb = u2f(Bk[i]); fa.x += fb.x; fa.y += fb.y; }
            R[i] = fa;
        }

        // ---- cross-kq reduction: kq 0->gsm, 2->part0, 3->part1; kq1 combines ----
        {
            float* dst = (kq == 0) ? gsm : (kq == 2) ? part0 : (kq == 3) ? part1 : (float*)0;
            if (dst) {
                #pragma unroll
                for (int bq = 0; bq < 2; ++bq) {
                    int b = b2 + bq;
                    float2 r01 = R[4 * bq + 0], r23 = R[4 * bq + 1];
                    float2 r45 = R[4 * bq + 2], r67 = R[4 * bq + 3];
                    *(float4*)(dst + b * GSTR + rg4)      = make_float4(r01.x, r01.y, r23.x, r23.y);
                    *(float4*)(dst + b * GSTR + 32 + rg4) = make_float4(r45.x, r45.y, r67.x, r67.y);
                }
            }
        }
        __syncthreads();   // sync1

        if (LAYER == 1) {
            if (tid < Bv && t + 1 < Tv)
                xr = __ldg(&x[(size_t)tid * Tv * Cv + (t + 1) * Cv + c]);
        }

        if (kq == 1) {
            #pragma unroll
            for (int bq = 0; bq < 2; ++bq) {
                int b = b2 + bq;
                #pragma unroll
                for (int hf = 0; hf < 2; ++hf) {
                    float4* g  = (float4*)(gsm   + b * GSTR + hf * 32 + rg4);
                    float4 p0  = *(float4*)(part0 + b * GSTR + hf * 32 + rg4);
                    float4 p1  = *(float4*)(part1 + b * GSTR + hf * 32 + rg4);
                    float2 ra  = R[4 * bq + 2 * hf], rb = R[4 * bq + 2 * hf + 1];
                    float4 a = *g;
                    a.x += p0.x + p1.x + ra.x;
                    a.y += p0.y + p1.y + ra.y;
                    a.z += p0.z + p1.z + rb.x;
                    a.w += p0.w + p1.w + rb.y;
                    *g = a;
                }
            }
        }
        __syncthreads();   // sync2: gsm final

        // ---- activations + state update: thread -> (b = lane, j = warp) ----
        {
            const float* gr = gsm + ab * GSTR;
            float vi = gr[pbase     ] + bsum[      aj];
            float vf = gr[pbase +  8] + bsum[16 + aj];
            float vg = gr[pbase + 16] + bsum[32 + aj];
            float vo = gr[pbase + 24] + bsum[48 + aj];
            if (LAYER == 1) {
                float xv = xs[ab];
                vi = fmaf(xv, wih1s[     aj], vi);
                vf = fmaf(xv, wih1s[16 + aj], vf);
                vg = fmaf(xv, wih1s[32 + aj], vg);
                vo = fmaf(xv, wih1s[48 + aj], vo);
            }
            float iv = sig_(vi), fv = sig_(vf), gv = tanh_(vg), ov = sig_(vo);
            float cn = fmaf(fv, c_s[tid], iv * gv);
            c_s[tid] = cn;
            float hn = ov * tanh_(cn);
            size_t hoff = ((size_t)c * Hv + jbase + aj) * Bv + ab;   // coalesced
            g_hbuf[(size_t)(t & 1) * (Cv * Hv * Bv) + hoff] = hn;
            if (LAYER == 1)
                g_h1[(((size_t)t * Cv + c) * Hv + jbase + aj) * Bv + ab] = hn;
            else
                part0[aj * 33 + ab] = hn * wlin16[aj];   // head staging (part0 dead here)
        }

        // ---- channel barrier; L2 hides ih(t+1) inside the wait window ----
        if (LAYER == 1) {
            chan_barrier(c, lsense);
        } else {
            __syncthreads();                       // entry: hn stores issued block-wide
            bool leader = false;
            if (tid == 0) {
                __threadfence();                   // release
                unsigned a = atomicAdd(&g_cnt[c], 1u);
                if (a == 15u) {
                    *(volatile unsigned*)&g_cnt[c] = 0u;
                    __threadfence();
                    *(volatile unsigned*)&g_sense[c] = lsense ^ 1u;
                    leader = true;
                }
            }
            CP_WAIT0();                            // h1[t+1] chunks landed
            __syncthreads();                       // all chunks visible
            if (t + 1 < Tv) {                      // ih matvec for t+1 (hidden work)
                #pragma unroll
                for (int i = 0; i < 8; ++i) Bk[i] = 0ull;
                matvec8x2(Bk, Wih_s + kq * 4096, h1_s + kq * 2048, rg4, b2);
            }
            if (tid == 0 && !leader) {
                while (*(volatile unsigned*)&g_sense[c] == lsense) { __nanosleep(20); }
                __threadfence();                   // acquire
            }
            lsense ^= 1u;
            __syncthreads();                       // exit
        }

        // ---- reload full h[t] for this channel into h_s[k][b] ----
        {
            const float4* src = (const float4*)(g_hbuf + (size_t)(t & 1) * (Cv * Hv * Bv)
                                                        + (size_t)c * Hv * Bv);
            float4* dst = (float4*)h_s;
            #pragma unroll
            for (int i = 0; i < 4; ++i)
                dst[tid + i * 512] = __ldcg(src + tid + i * 512);
        }

        // ---- head partial: one warp sums this CTA's 16 j-lanes, stores off-path ----
        if (LAYER == 2 && tid < 32) {
            float s = 0.0f;
            #pragma unroll
            for (int j = 0; j < 16; ++j) s += part0[j * 33 + tid];
            g_opart[(((size_t)t * Cv + c) * 16 + rank) * Bv + tid] = s;
        }
        // loop-top __syncthreads orders h_s reload + part0 reads before next compute
    }
}

// ---------------- epilogue: out[b][t][c] = blin[c] + sum_rank opart ----------------
__global__ __launch_bounds__(256)
void head_kernel(const float* __restrict__ blin, float* __restrict__ out)
{
    int i  = blockIdx.x * 256 + threadIdx.x;
    int b  = i & 31;
    int tc = i >> 5;
    int c  = tc & (Cv - 1);
    int t  = tc >> 3;
    const float* p = g_opart + (size_t)tc * 16 * Bv + b;
    float s = __ldg(&blin[c]);
    #pragma unroll
    for (int r = 0; r < 16; ++r) s += p[r * Bv];
    out[(size_t)b * Tv * Cv + t * Cv + c] = s;
}

// ---------------- launch ----------------
extern "C" void kernel_launch(void* const* d_in, const int* in_sizes, int n_in,
                              void* d_out, int out_size)
{
    const float* x    = (const float*)d_in[0];
    const float* Wih1 = (const float*)d_in[1];
    const float* Whh1 = (const float*)d_in[2];
    const float* bih1 = (const float*)d_in[3];
    const float* bhh1 = (const float*)d_in[4];
    const float* Wih2 = (const float*)d_in[5];
    const float* Whh2 = (const float*)d_in[6];
    const float* bih2 = (const float*)d_in[7];
    const float* bhh2 = (const float*)d_in[8];
    const float* Wlin = (const float*)d_in[9];
    const float* blin = (const float*)d_in[10];
    float* out = (float*)d_out;

    (void)in_sizes; (void)n_in; (void)out_size;

    cudaFuncSetAttribute(lstm_kernel<1>, cudaFuncAttributeMaxDynamicSharedMemorySize, SM_BYTES);
    cudaFuncSetAttribute(lstm_kernel<2>, cudaFuncAttributeMaxDynamicSharedMemorySize, SM_BYTES);

    lstm_kernel<1><<<128, 512, SM_BYTES>>>(x, Wih1, Whh1, bih1, bhh1, nullptr);
    lstm_kernel<2><<<128, 512, SM_BYTES>>>(nullptr, Wih2, Whh2, bih2, bhh2, Wlin);
    head_kernel<<<512, 256>>>(blin, out);
}